// round 15
// baseline (speedup 1.0000x reference)
#include <cuda_runtime.h>
#include <cuda_bf16.h>
#include <cstdint>
#include <math.h>

#define NN 20000
#define D  256
#define EE 500000
#define NR 4
#define NBKT (NR * NN)
#define NBLK 157                 // 128-row layout tiles per 20000-row half
#define RB64 313                 // 64-row GEMM blocks per half
#define TILE_ELEMS 8192          // 128 rows x 64 k bf16
#define TILE_BYTES 16384
#define ATILES (NBLK * 4)        // tiles per 256-wide half-array (628)
#define HALF_OFF ((size_t)ATILES * TILE_ELEMS)
#define SCAN_B 1024
#define SCAN_NB ((NBKT + SCAN_B - 1) / SCAN_B)   // 79

// ---------------- scratch (no allocations allowed) ----------------
__device__ int g_deg[NBKT];
__device__ int g_rowptr[NBKT];
__device__ int g_total;
__device__ int g_adj[EE];

__device__ __nv_bfloat16 g_xhi[ATILES * TILE_ELEMS], g_xlo[ATILES * TILE_ELEMS];
__device__ __nv_bfloat16 g_agghi[2 * ATILES * TILE_ELEMS], g_agglo[2 * ATILES * TILE_ELEMS];
__device__ __nv_bfloat16 g_hhi[2 * ATILES * TILE_ELEMS], g_hlo[2 * ATILES * TILE_ELEMS];
__device__ __nv_bfloat16 g_ehi[2 * ATILES * TILE_ELEMS], g_elo[2 * ATILES * TILE_ELEMS];
__device__ float g_f1[NN * D];
// B: [gemm 5][colblock 2][kc 8][tile]
__device__ __nv_bfloat16 g_Bhi[5 * 16 * TILE_ELEMS], g_Blo[5 * 16 * TILE_ELEMS];

// ================= helpers =================
__device__ __forceinline__ uint32_t smem_u32(const void* p) {
    uint32_t a;
    asm("{ .reg .u64 t; cvta.to.shared.u64 t, %1; cvt.u32.u64 %0, t; }" : "=r"(a) : "l"(p));
    return a;
}
// byte offset of (row r, col k) inside a 128x64 bf16 tile with XOR-swizzled 128B rows
__device__ __forceinline__ uint32_t tileoff_b(int r, int k) {
    return (uint32_t)(r * 128 + ((((k >> 3) ^ r) & 7) << 4) + ((k & 7) << 1));
}
#define MBAR_INIT(addr, cnt) \
    asm volatile("mbarrier.init.shared.b64 [%0], %1;" :: "r"(addr), "r"(cnt) : "memory")
#define MBAR_ARRIVE(addr) \
    asm volatile("mbarrier.arrive.shared.b64 _, [%0];" :: "r"(addr) : "memory")
#define MBAR_EXPECT_TX(addr, bytes) \
    asm volatile("mbarrier.arrive.expect_tx.shared.b64 _, [%0], %1;" :: "r"(addr), "r"(bytes) : "memory")
#define MBAR_WAIT(addr, parity) do {                                              \
    uint32_t _m = (addr); uint32_t _p = (parity); uint32_t _done;                 \
    asm volatile("{\n\t.reg .pred p;\n\t"                                         \
        "mbarrier.try_wait.parity.acquire.cta.shared::cta.b64 p, [%1], %2;\n\t"   \
        "selp.b32 %0, 1, 0, p;\n\t}"                                              \
        : "=r"(_done) : "r"(_m), "r"(_p) : "memory");                             \
    if (!_done) {                                                                 \
        asm volatile("{\n\t.reg .pred P1;\n\t"                                    \
            "WL_%=:\n\t"                                                          \
            "mbarrier.try_wait.parity.acquire.cta.shared::cta.b64 P1, [%0], %1, 0x989680;\n\t" \
            "@P1 bra.uni WD_%=;\n\t"                                              \
            "bra.uni WL_%=;\n\t"                                                  \
            "WD_%=:\n\t}" :: "r"(_m), "r"(_p) : "memory");                        \
    }                                                                             \
} while (0)
__device__ __forceinline__ void bulk_g2s(uint32_t dst, const void* src, uint32_t bytes, uint32_t mbar) {
    asm volatile("cp.async.bulk.shared::cluster.global.mbarrier::complete_tx::bytes [%0], [%1], %2, [%3];"
                 :: "r"(dst), "l"(__cvta_generic_to_global(src)), "r"(bytes), "r"(mbar) : "memory");
}
__device__ __forceinline__ void ldsm4(uint32_t* r, uint32_t addr) {
    asm volatile("ldmatrix.sync.aligned.m8n8.x4.shared.b16 {%0,%1,%2,%3}, [%4];"
                 : "=r"(r[0]), "=r"(r[1]), "=r"(r[2]), "=r"(r[3]) : "r"(addr));
}
__device__ __forceinline__ void mma16816(float* c, const uint32_t* a, uint32_t b0, uint32_t b1) {
    asm volatile("mma.sync.aligned.m16n8k16.row.col.f32.bf16.bf16.f32 "
                 "{%0,%1,%2,%3}, {%4,%5,%6,%7}, {%8,%9}, {%0,%1,%2,%3};"
                 : "+f"(c[0]), "+f"(c[1]), "+f"(c[2]), "+f"(c[3])
                 : "r"(a[0]), "r"(a[1]), "r"(a[2]), "r"(a[3]), "r"(b0), "r"(b1));
}
__device__ __forceinline__ void add_bf2(float* a, uint32_t h, uint32_t l) {
    __nv_bfloat162 hh = *(__nv_bfloat162*)&h, ll = *(__nv_bfloat162*)&l;
    float2 fh = __bfloat1622float2(hh), fl = __bfloat1622float2(ll);
    a[0] += fh.x + fl.x;
    a[1] += fh.y + fl.y;
}
__device__ __forceinline__ uint32_t pack_hi(float v0, float v1, uint32_t& lo_out) {
    __nv_bfloat16 h0 = __float2bfloat16(v0);
    __nv_bfloat16 h1 = __float2bfloat16(v1);
    __nv_bfloat16 l0 = __float2bfloat16(v0 - __bfloat162float(h0));
    __nv_bfloat16 l1 = __float2bfloat16(v1 - __bfloat162float(h1));
    lo_out = (uint32_t)__bfloat16_as_ushort(l0) | ((uint32_t)__bfloat16_as_ushort(l1) << 16);
    return (uint32_t)__bfloat16_as_ushort(h0) | ((uint32_t)__bfloat16_as_ushort(h1) << 16);
}

// ================= CSR build =================
__global__ void zero_deg_kernel() {
    int i = blockIdx.x * blockDim.x + threadIdx.x;
    if (i < NBKT) g_deg[i] = 0;
    if (i == 0) g_total = 0;
}
// 2 edges per thread, int2 loads (EE even, 8B-aligned)
__global__ void hist_kernel(const int* __restrict__ ei, const int* __restrict__ et) {
    int i = (blockIdx.x * blockDim.x + threadIdx.x) * 2;
    if (i >= EE) return;
    int2 rr = *(const int2*)(et + i);
    int2 ss = *(const int2*)(ei + i);
    if (rr.x < NR) atomicAdd(&g_deg[rr.x * NN + ss.x], 1);
    if (rr.y < NR) atomicAdd(&g_deg[rr.y * NN + ss.y], 1);
}
__global__ void scan_fused() {
    __shared__ int sh[SCAN_B];
    __shared__ int boff;
    const int tid = threadIdx.x;
    const int idx = blockIdx.x * SCAN_B + tid;
    int v = (idx < NBKT) ? g_deg[idx] : 0;
    sh[tid] = v;
    __syncthreads();
#pragma unroll
    for (int off = 1; off < SCAN_B; off <<= 1) {
        int t = (tid >= off) ? sh[tid - off] : 0;
        __syncthreads();
        sh[tid] += t;
        __syncthreads();
    }
    if (tid == SCAN_B - 1) boff = atomicAdd(&g_total, sh[tid]);
    __syncthreads();
    if (idx < NBKT) g_rowptr[idx] = boff + sh[tid] - v;   // exclusive within partition
}
// scatter bumps rowptr in place; afterwards rowptr[b] == end of bucket b.
__global__ void scatter_kernel(const int* __restrict__ ei, const int* __restrict__ et) {
    int i = (blockIdx.x * blockDim.x + threadIdx.x) * 2;
    if (i >= EE) return;
    int2 rr = *(const int2*)(et + i);
    int2 ss = *(const int2*)(ei + i);
    int2 dd = *(const int2*)(ei + EE + i);
    if (rr.x < NR) {
        int slot = atomicAdd(&g_rowptr[rr.x * NN + ss.x], 1);
        g_adj[slot] = dd.x;
    }
    if (rr.y < NR) {
        int slot = atomicAdd(&g_rowptr[rr.y * NN + ss.y], 1);
        g_adj[slot] = dd.y;
    }
}

// ================= conversions (pure; tiled+swizzled) =================
#define XCHUNKS (NN * 32)
#define BCHUNKS (5 * 16 * 1024)
__global__ void conv_all(const float* __restrict__ x,
                         const float* __restrict__ relW, const float* __restrict__ rootW,
                         const float* __restrict__ fc1w) {
    int gid = blockIdx.x * blockDim.x + threadIdx.x;
    if (gid < XCHUNKS) {
        int row = gid >> 5, cc = gid & 31;
        int kc = cc >> 3, c = cc & 7;
        int r = row & 127;
        const float* src = x + (size_t)row * 256 + cc * 8;
        float4 f0 = *(const float4*)src;
        float4 f1 = *(const float4*)(src + 4);
        uint4 hi, lo;
        hi.x = pack_hi(f0.x, f0.y, lo.x);
        hi.y = pack_hi(f0.z, f0.w, lo.y);
        hi.z = pack_hi(f1.x, f1.y, lo.z);
        hi.w = pack_hi(f1.z, f1.w, lo.w);
        size_t off = (size_t)((row >> 7) * 4 + kc) * TILE_BYTES + r * 128 + (((c ^ r) & 7) << 4);
        *(uint4*)((char*)g_xhi + off) = hi;
        *(uint4*)((char*)g_xlo + off) = lo;
        return;
    }
    int bid = gid - XCHUNKS;
    if (bid >= BCHUNKS) return;
    int g = bid >> 14;
    int r1 = bid & 16383;
    int cb = r1 >> 13;
    int r2 = r1 & 8191;
    int kc = r2 >> 10;
    int r3 = r2 & 1023;
    int row = r3 >> 3;
    int c = r3 & 7;
    int n = cb * 128 + row;
    int kbase = kc * 64 + c * 8;
    float v[8];
#pragma unroll
    for (int j = 0; j < 8; j++) {
        int k = kbase + j;
        if (g < 4)
            v[j] = (k < 256) ? relW[(((size_t)g * 5 + g) * 256 + k) * 256 + n]
                             : rootW[((size_t)g * 256 + (k - 256)) * 256 + n];
        else
            v[j] = fc1w[(size_t)k * 256 + n];
    }
    uint4 hi, lo;
    hi.x = pack_hi(v[0], v[1], lo.x);
    hi.y = pack_hi(v[2], v[3], lo.y);
    hi.z = pack_hi(v[4], v[5], lo.z);
    hi.w = pack_hi(v[6], v[7], lo.w);
    size_t off = (size_t)(g * 16 + cb * 8 + kc) * TILE_BYTES + row * 128 + (((c ^ row) & 7) << 4);
    *(uint4*)((char*)g_Bhi + off) = hi;
    *(uint4*)((char*)g_Blo + off) = lo;
}

// ================= fused CSR aggregation (tiled in/out) =================
__global__ void agg_csr(const __nv_bfloat16* __restrict__ inhiA, const __nv_bfloat16* __restrict__ inloA,
                        const __nv_bfloat16* __restrict__ inhiB, const __nv_bfloat16* __restrict__ inloB,
                        int relA, int relB,
                        __nv_bfloat16* __restrict__ outhi, __nv_bfloat16* __restrict__ outlo) {
    int w = (blockIdx.x * blockDim.x + threadIdx.x) >> 5;
    int lane = threadIdx.x & 31;
    if (w >= 2 * NN) return;
    int half = (w >= NN);
    int node = w - half * NN;
    int rel = half ? relB : relA;
    const char* hib = (const char*)(half ? inhiB : inhiA);
    const char* lob = (const char*)(half ? inloB : inloA);
    int b = rel * NN + node;
    int deg = g_deg[b];
    int end = g_rowptr[b];       // post-scatter: rowptr[b] == end
    int beg = end - deg;
    const int kc = lane >> 3, cc = lane & 7;
    float acc[8];
#pragma unroll
    for (int i = 0; i < 8; i++) acc[i] = 0.0f;
    for (int j = beg; j < end; j++) {
        int d = g_adj[j];
        int r = d & 127;
        size_t tb = (size_t)((d >> 7) * 4 + kc) * TILE_BYTES + r * 128 + (((cc ^ r) & 7) << 4);
        uint4 vh = *(const uint4*)(hib + tb);
        uint4 vl = *(const uint4*)(lob + tb);
        add_bf2(acc + 0, vh.x, vl.x);
        add_bf2(acc + 2, vh.y, vl.y);
        add_bf2(acc + 4, vh.z, vl.z);
        add_bf2(acc + 6, vh.w, vl.w);
    }
    float inv = 1.0f / fmaxf((float)deg, 1.0f);
    uint4 oh, ol;
    oh.x = pack_hi(acc[0] * inv, acc[1] * inv, ol.x);
    oh.y = pack_hi(acc[2] * inv, acc[3] * inv, ol.y);
    oh.z = pack_hi(acc[4] * inv, acc[5] * inv, ol.z);
    oh.w = pack_hi(acc[6] * inv, acc[7] * inv, ol.w);
    int r = node & 127;
    size_t ob = (size_t)((half * NBLK + (node >> 7)) * 4 + kc) * TILE_BYTES
              + r * 128 + (((cc ^ r) & 7) << 4);
    *(uint4*)((char*)outhi + ob) = oh;
    *(uint4*)((char*)outlo + ob) = ol;
}

// ================= bulk-copy MMA GEMM: 64x128 tiles, 48KB stages x4 =================
#define NSTAGE 4
#define STAGE_BYTES 49152
#define SMEM_BYTES (NSTAGE * STAGE_BYTES)   // 196608
#define NWARP 16

__global__ __launch_bounds__(512, 1)
void gemm_mma(const __nv_bfloat16* __restrict__ A1hi, const __nv_bfloat16* __restrict__ A1lo,
              const __nv_bfloat16* __restrict__ A2hi, const __nv_bfloat16* __restrict__ A2lo,
              int a2_global,
              const __nv_bfloat16* __restrict__ B0hi, const __nv_bfloat16* __restrict__ B0lo,
              const float* __restrict__ bias0,
              const __nv_bfloat16* __restrict__ B1hi, const __nv_bfloat16* __restrict__ B1lo,
              const float* __restrict__ bias1,
              float* __restrict__ Cf, __nv_bfloat16* __restrict__ Chi, __nv_bfloat16* __restrict__ Clo) {
    extern __shared__ __align__(16) char smem[];
    __shared__ __align__(8) uint64_t mbar[2 * NSTAGE];   // [full_s, empty_s] pairs
    const uint32_t sb = smem_u32(smem);
    const uint32_t sbar = smem_u32(mbar);
    const int tid = threadIdx.x;
    const int lane = tid & 31;
    const int wid = tid >> 5;                // 0..15
    const int wm = wid >> 2, wn = wid & 3;   // 4x4 warp grid, warp tile 16x32
    const int gblk = blockIdx.x;
    const int half = (gblk >= RB64) ? 1 : 0;
    const int lblk = gblk - half * RB64;     // 64-row block within half
    const int rb128 = lblk >> 1;             // layout tile row-block
    const int sub = lblk & 1;                // which 64-row half of the tile
    const int cb = blockIdx.y;
    const __nv_bfloat16* Bhi = half ? B1hi : B0hi;
    const __nv_bfloat16* Blo = half ? B1lo : B0lo;
    const float* bias = half ? bias1 : bias0;

    if (tid == 0) {
#pragma unroll
        for (int s = 0; s < NSTAGE; s++) {
            MBAR_INIT(sbar + s * 16, 1);          // full: tx-based
            MBAR_INIT(sbar + s * 16 + 8, NWARP);  // empty: one arrive per warp
        }
    }
    __syncthreads();

    auto issue = [&](int c) {
        const int s = c & (NSTAGE - 1);
        const uint32_t bar = sbar + s * 16;
        const uint32_t dst = sb + s * STAGE_BYTES;
        const int kc = (c < 4) ? c : (c - 4);
        size_t atile;
        const __nv_bfloat16 *ahb, *alb;
        if (c < 4) {
            atile = ((size_t)(half * NBLK + rb128) * 4 + kc);
            ahb = A1hi; alb = A1lo;
        } else {
            atile = a2_global ? ((size_t)(half * NBLK + rb128) * 4 + kc)
                              : ((size_t)rb128 * 4 + kc);
            ahb = A2hi; alb = A2lo;
        }
        const __nv_bfloat16* ah = ahb + atile * TILE_ELEMS + sub * 4096;   // 8KB slice
        const __nv_bfloat16* al = alb + atile * TILE_ELEMS + sub * 4096;
        const __nv_bfloat16* bh = Bhi + (size_t)(cb * 8 + c) * TILE_ELEMS;
        const __nv_bfloat16* bl = Blo + (size_t)(cb * 8 + c) * TILE_ELEMS;
        MBAR_EXPECT_TX(bar, STAGE_BYTES);
        bulk_g2s(dst,         ah, 8192,       bar);
        bulk_g2s(dst + 8192,  al, 8192,       bar);
        bulk_g2s(dst + 16384, bh, TILE_BYTES, bar);
        bulk_g2s(dst + 32768, bl, TILE_BYTES, bar);
    };

    if (tid == 0) { issue(0); issue(1); issue(2); issue(3); }

    float acc[4][4];
#pragma unroll
    for (int b = 0; b < 4; b++)
#pragma unroll
        for (int c = 0; c < 4; c++) acc[b][c] = 0.0f;

    const int rA0 = wm * 16 + (lane & 15);
    const int rB0 = wn * 32 + (lane & 15);
    const int ksub = (lane >> 4) << 3;

#pragma unroll 1
    for (int c = 0; c < 8; c++) {
        const int s = c & (NSTAGE - 1);
        MBAR_WAIT(sbar + s * 16, (c >> 2) & 1);          // full
        const uint32_t st = sb + s * STAGE_BYTES;
#pragma unroll
        for (int kk = 0; kk < 4; kk++) {
            const int kof = kk * 16 + ksub;
            uint32_t ahf[4], alf[4], bhf[2][4], blf[2][4];
            ldsm4(ahf, st + tileoff_b(rA0, kof));
            ldsm4(alf, st + 8192 + tileoff_b(rA0, kof));
#pragma unroll
            for (int np = 0; np < 2; np++) {
                ldsm4(bhf[np], st + 16384 + tileoff_b(rB0 + np * 16, kof));
                ldsm4(blf[np], st + 32768 + tileoff_b(rB0 + np * 16, kof));
            }
#pragma unroll
            for (int np = 0; np < 2; np++) {
                mma16816(acc[np * 2 + 0], ahf, bhf[np][0], bhf[np][2]);
                mma16816(acc[np * 2 + 1], ahf, bhf[np][1], bhf[np][3]);
                mma16816(acc[np * 2 + 0], ahf, blf[np][0], blf[np][2]);
                mma16816(acc[np * 2 + 1], ahf, blf[np][1], blf[np][3]);
                mma16816(acc[np * 2 + 0], alf, bhf[np][0], bhf[np][2]);
                mma16816(acc[np * 2 + 1], alf, bhf[np][1], bhf[np][3]);
            }
        }
        if (lane == 0) MBAR_ARRIVE(sbar + s * 16 + 8);       // warp done with stage s
        if (tid == 0 && c + NSTAGE < 8) {
            MBAR_WAIT(sbar + s * 16 + 8, (c >> 2) & 1);      // all warps done with stage s
            issue(c + NSTAGE);
        }
    }

    // ---------------- epilogue: direct global stores ----------------
    const int tq = lane & 3, trr = lane >> 2;
    float bv[4][2];
#pragma unroll
    for (int ni = 0; ni < 4; ni++) {
        int colg = cb * 128 + wn * 32 + ni * 8 + tq * 2;
        bv[ni][0] = __ldg(&bias[colg]);
        bv[ni][1] = __ldg(&bias[colg + 1]);
    }
#pragma unroll
    for (int hr = 0; hr < 2; hr++) {
        const int r = wm * 16 + trr + hr * 8;        // row within 64-row block
        const int rl = lblk * 64 + r;                // row within half
        if (rl >= NN) continue;
#pragma unroll
        for (int ni = 0; ni < 4; ni++) {
            float v0 = fmaxf(acc[ni][hr * 2 + 0] + bv[ni][0], 0.0f);
            float v1 = fmaxf(acc[ni][hr * 2 + 1] + bv[ni][1], 0.0f);
            const int colg = cb * 128 + wn * 32 + ni * 8 + tq * 2;
            if (Cf)
                *(float2*)(Cf + (size_t)(half * NN + rl) * 256 + colg) = make_float2(v0, v1);
            if (Chi) {
                uint32_t lo32;
                uint32_t hi32 = pack_hi(v0, v1, lo32);
                const int kcol = colg >> 6, kl = colg & 63;
                const size_t off = (size_t)((half * NBLK + (rl >> 7)) * 4 + kcol) * TILE_BYTES
                                 + tileoff_b(rl & 127, kl);
                *(uint32_t*)((char*)Chi + off) = hi32;
                *(uint32_t*)((char*)Clo + off) = lo32;
            }
        }
    }
}

// ---------------- fc2 (256->16) + log_softmax ----------------
__global__ void fc2_lsm_kernel(const float* __restrict__ H,
                               const float* __restrict__ W,
                               const float* __restrict__ b,
                               float* __restrict__ out, int M) {
    __shared__ float sw[16 * 256];
    const int tid = threadIdx.x;
    for (int i = tid; i < 16 * 256; i += blockDim.x) {
        int n = i >> 8, k = i & 255;
        sw[i] = W[k * 16 + n];
    }
    __syncthreads();

    const int warp = tid >> 5;
    const int lane = tid & 31;
    const int row = blockIdx.x * 8 + warp;
    if (row >= M) return;

    const float* hrow = H + (size_t)row * D;
    float acc[16];
#pragma unroll
    for (int n = 0; n < 16; n++) acc[n] = 0.0f;
#pragma unroll
    for (int kk = 0; kk < 8; kk++) {
        int k = lane + 32 * kk;
        float hv = hrow[k];
#pragma unroll
        for (int n = 0; n < 16; n++) acc[n] = fmaf(hv, sw[n * 256 + k], acc[n]);
    }
#pragma unroll
    for (int n = 0; n < 16; n++) {
#pragma unroll
        for (int o = 16; o > 0; o >>= 1)
            acc[n] += __shfl_xor_sync(0xFFFFFFFFu, acc[n], o);
    }
    if (lane == 0) {
        float v[16];
        float mx = -1e30f;
#pragma unroll
        for (int n = 0; n < 16; n++) { v[n] = acc[n] + b[n]; mx = fmaxf(mx, v[n]); }
        float s = 0.0f;
#pragma unroll
        for (int n = 0; n < 16; n++) s += expf(v[n] - mx);
        float l = logf(s);
        float* orow = out + (size_t)row * 16;
#pragma unroll
        for (int n = 0; n < 16; n++) orow[n] = v[n] - mx - l;
    }
}

// ================= host =================
template <typename T>
static T* sym(const void* symbol) {
    void* p = nullptr;
    cudaGetSymbolAddress(&p, symbol);
    return (T*)p;
}

extern "C" void kernel_launch(void* const* d_in, const int* in_sizes, int n_in,
                              void* d_out, int out_size) {
    const float* x     = (const float*)d_in[0];
    const int*   ei    = (const int*)  d_in[1];
    const int*   et    = (const int*)  d_in[2];
    const float* relW  = (const float*)d_in[3];
    const float* rootW = (const float*)d_in[4];
    const float* bias  = (const float*)d_in[5];
    const float* fc1w  = (const float*)d_in[6];
    const float* fc1b  = (const float*)d_in[7];
    const float* fc2w  = (const float*)d_in[8];
    const float* fc2b  = (const float*)d_in[9];
    float* out = (float*)d_out;

    __nv_bfloat16* xhi = sym<__nv_bfloat16>(g_xhi);
    __nv_bfloat16* xlo = sym<__nv_bfloat16>(g_xlo);
    __nv_bfloat16* ahi = sym<__nv_bfloat16>(g_agghi);
    __nv_bfloat16* alo = sym<__nv_bfloat16>(g_agglo);
    __nv_bfloat16* hhi = sym<__nv_bfloat16>(g_hhi);
    __nv_bfloat16* hlo = sym<__nv_bfloat16>(g_hlo);
    __nv_bfloat16* ehi = sym<__nv_bfloat16>(g_ehi);
    __nv_bfloat16* elo = sym<__nv_bfloat16>(g_elo);
    __nv_bfloat16* Bhi = sym<__nv_bfloat16>(g_Bhi);
    __nv_bfloat16* Blo = sym<__nv_bfloat16>(g_Blo);
    float* f1 = sym<float>(g_f1);

    cudaFuncSetAttribute(gemm_mma, cudaFuncAttributeMaxDynamicSharedMemorySize, SMEM_BYTES);

    const size_t GB = 16 * TILE_ELEMS;   // B elems per gemm

    // Fork: CSR chain on s0, conversions on s2 (independent).
    cudaStream_t s0 = 0, s2;
    cudaStreamCreate(&s2);
    cudaEvent_t evFork, evJoin;
    cudaEventCreateWithFlags(&evFork, cudaEventDisableTiming);
    cudaEventCreateWithFlags(&evJoin, cudaEventDisableTiming);

    cudaEventRecord(evFork, s0);
    cudaStreamWaitEvent(s2, evFork, 0);
    conv_all<<<(XCHUNKS + BCHUNKS + 255) / 256, 256, 0, s2>>>(x, relW, rootW, fc1w);
    cudaEventRecord(evJoin, s2);

    // main stream: CSR build
    zero_deg_kernel<<<(NBKT + 255) / 256, 256, 0, s0>>>();
    hist_kernel<<<(EE / 2 + 255) / 256, 256, 0, s0>>>(ei, et);
    scan_fused<<<SCAN_NB, SCAN_B, 0, s0>>>();
    scatter_kernel<<<(EE / 2 + 255) / 256, 256, 0, s0>>>(ei, et);

    // join: agg needs CSR + xhi/xlo; gemm needs B tiles
    cudaStreamWaitEvent(s0, evJoin, 0);

    const dim3 ggrid2(2 * RB64, 2);
    const dim3 ggrid1(RB64, 2);
    const int aggBlocks = (2 * NN * 32 + 255) / 256;

    // stage A (convs {0,2} on x)
    agg_csr<<<aggBlocks, 256, 0, s0>>>(xhi, xlo, xhi, xlo, 0, 2, ahi, alo);
    gemm_mma<<<ggrid2, 512, SMEM_BYTES, s0>>>(
        ahi, alo, xhi, xlo, /*a2_global=*/0,
        Bhi + 0 * GB, Blo + 0 * GB, bias + 0 * 256,
        Bhi + 2 * GB, Blo + 2 * GB, bias + 2 * 256,
        nullptr, hhi, hlo);

    // stage B (convs {1,3} on stage-A halves)
    agg_csr<<<aggBlocks, 256, 0, s0>>>(hhi, hlo, hhi + HALF_OFF, hlo + HALF_OFF, 1, 3, ahi, alo);
    gemm_mma<<<ggrid2, 512, SMEM_BYTES, s0>>>(
        ahi, alo, hhi, hlo, /*a2_global=*/1,
        Bhi + 1 * GB, Blo + 1 * GB, bias + 1 * 256,
        Bhi + 3 * GB, Blo + 3 * GB, bias + 3 * 256,
        nullptr, ehi, elo);

    // fc1: [e0 | e1] -> f1 (f32, relu)
    gemm_mma<<<ggrid1, 512, SMEM_BYTES, s0>>>(
        ehi, elo, ehi + HALF_OFF, elo + HALF_OFF, /*a2_global=*/0,
        Bhi + 4 * GB, Blo + 4 * GB, fc1b,
        Bhi + 4 * GB, Blo + 4 * GB, fc1b,
        f1, nullptr, nullptr);

    // fc2 + log_softmax
    fc2_lsm_kernel<<<(NN + 7) / 8, 256, 0, s0>>>(f1, fc2w, fc2b, out, NN);
}

// round 16
// speedup vs baseline: 1.4958x; 1.4958x over previous
#include <cuda_runtime.h>
#include <cuda_bf16.h>
#include <cstdint>
#include <math.h>

#define NN 20000
#define D  256
#define EE 500000
#define NR 4
#define NBKT (NR * NN)
#define NBLK 157                 // 128-row layout tiles per 20000-row half
#define RB64 313                 // 64-row GEMM blocks per half
#define TILE_ELEMS 8192          // 128 rows x 64 k bf16
#define TILE_BYTES 16384
#define ATILES (NBLK * 4)        // tiles per 256-wide half-array (628)
#define HALF_OFF ((size_t)ATILES * TILE_ELEMS)
#define SCAN_B 1024
#define SCAN_NB ((NBKT + SCAN_B - 1) / SCAN_B)   // 79

// ---------------- scratch (no allocations allowed) ----------------
__device__ int g_deg[NBKT];
__device__ int g_rowptr[NBKT];
__device__ int g_total;
__device__ int g_adj[EE];

__device__ __nv_bfloat16 g_xhi[ATILES * TILE_ELEMS], g_xlo[ATILES * TILE_ELEMS];
__device__ __nv_bfloat16 g_agghi[2 * ATILES * TILE_ELEMS], g_agglo[2 * ATILES * TILE_ELEMS];
__device__ __nv_bfloat16 g_hhi[2 * ATILES * TILE_ELEMS], g_hlo[2 * ATILES * TILE_ELEMS];
__device__ __nv_bfloat16 g_ehi[2 * ATILES * TILE_ELEMS], g_elo[2 * ATILES * TILE_ELEMS];
__device__ float g_f1[NN * D];
// B: [gemm 5][colblock 2][kc 8][tile]
__device__ __nv_bfloat16 g_Bhi[5 * 16 * TILE_ELEMS], g_Blo[5 * 16 * TILE_ELEMS];

// ================= helpers =================
__device__ __forceinline__ uint32_t smem_u32(const void* p) {
    uint32_t a;
    asm("{ .reg .u64 t; cvta.to.shared.u64 t, %1; cvt.u32.u64 %0, t; }" : "=r"(a) : "l"(p));
    return a;
}
// byte offset of (row r, col k) inside a 128x64 bf16 tile with XOR-swizzled 128B rows
__device__ __forceinline__ uint32_t tileoff_b(int r, int k) {
    return (uint32_t)(r * 128 + ((((k >> 3) ^ r) & 7) << 4) + ((k & 7) << 1));
}
#define MBAR_INIT(addr, cnt) \
    asm volatile("mbarrier.init.shared.b64 [%0], %1;" :: "r"(addr), "r"(cnt) : "memory")
#define MBAR_ARRIVE(addr) \
    asm volatile("mbarrier.arrive.shared.b64 _, [%0];" :: "r"(addr) : "memory")
#define MBAR_EXPECT_TX(addr, bytes) \
    asm volatile("mbarrier.arrive.expect_tx.shared.b64 _, [%0], %1;" :: "r"(addr), "r"(bytes) : "memory")
#define MBAR_WAIT(addr, parity) do {                                              \
    uint32_t _m = (addr); uint32_t _p = (parity); uint32_t _done;                 \
    asm volatile("{\n\t.reg .pred p;\n\t"                                         \
        "mbarrier.try_wait.parity.acquire.cta.shared::cta.b64 p, [%1], %2;\n\t"   \
        "selp.b32 %0, 1, 0, p;\n\t}"                                              \
        : "=r"(_done) : "r"(_m), "r"(_p) : "memory");                             \
    if (!_done) {                                                                 \
        asm volatile("{\n\t.reg .pred P1;\n\t"                                    \
            "WL_%=:\n\t"                                                          \
            "mbarrier.try_wait.parity.acquire.cta.shared::cta.b64 P1, [%0], %1, 0x989680;\n\t" \
            "@P1 bra.uni WD_%=;\n\t"                                              \
            "bra.uni WL_%=;\n\t"                                                  \
            "WD_%=:\n\t}" :: "r"(_m), "r"(_p) : "memory");                        \
    }                                                                             \
} while (0)
__device__ __forceinline__ void bulk_g2s(uint32_t dst, const void* src, uint32_t bytes, uint32_t mbar) {
    asm volatile("cp.async.bulk.shared::cluster.global.mbarrier::complete_tx::bytes [%0], [%1], %2, [%3];"
                 :: "r"(dst), "l"(__cvta_generic_to_global(src)), "r"(bytes), "r"(mbar) : "memory");
}
__device__ __forceinline__ void ldsm4(uint32_t* r, uint32_t addr) {
    asm volatile("ldmatrix.sync.aligned.m8n8.x4.shared.b16 {%0,%1,%2,%3}, [%4];"
                 : "=r"(r[0]), "=r"(r[1]), "=r"(r[2]), "=r"(r[3]) : "r"(addr));
}
__device__ __forceinline__ void mma16816(float* c, const uint32_t* a, uint32_t b0, uint32_t b1) {
    asm volatile("mma.sync.aligned.m16n8k16.row.col.f32.bf16.bf16.f32 "
                 "{%0,%1,%2,%3}, {%4,%5,%6,%7}, {%8,%9}, {%0,%1,%2,%3};"
                 : "+f"(c[0]), "+f"(c[1]), "+f"(c[2]), "+f"(c[3])
                 : "r"(a[0]), "r"(a[1]), "r"(a[2]), "r"(a[3]), "r"(b0), "r"(b1));
}
__device__ __forceinline__ void add_bf2(float* a, uint32_t h, uint32_t l) {
    __nv_bfloat162 hh = *(__nv_bfloat162*)&h, ll = *(__nv_bfloat162*)&l;
    float2 fh = __bfloat1622float2(hh), fl = __bfloat1622float2(ll);
    a[0] += fh.x + fl.x;
    a[1] += fh.y + fl.y;
}
__device__ __forceinline__ uint32_t pack_hi(float v0, float v1, uint32_t& lo_out) {
    __nv_bfloat16 h0 = __float2bfloat16(v0);
    __nv_bfloat16 h1 = __float2bfloat16(v1);
    __nv_bfloat16 l0 = __float2bfloat16(v0 - __bfloat162float(h0));
    __nv_bfloat16 l1 = __float2bfloat16(v1 - __bfloat162float(h1));
    lo_out = (uint32_t)__bfloat16_as_ushort(l0) | ((uint32_t)__bfloat16_as_ushort(l1) << 16);
    return (uint32_t)__bfloat16_as_ushort(h0) | ((uint32_t)__bfloat16_as_ushort(h1) << 16);
}

// ================= CSR build =================
__global__ void zero_deg_kernel() {
    int i = blockIdx.x * blockDim.x + threadIdx.x;
    if (i < NBKT) g_deg[i] = 0;
    if (i == 0) g_total = 0;
}
__global__ void hist_kernel(const int* __restrict__ ei, const int* __restrict__ et) {
    int i = blockIdx.x * blockDim.x + threadIdx.x;
    if (i >= EE) return;
    int r = et[i];
    if (r >= NR) return;
    atomicAdd(&g_deg[r * NN + ei[i]], 1);
}
__global__ void scan_fused() {
    __shared__ int sh[SCAN_B];
    __shared__ int boff;
    const int tid = threadIdx.x;
    const int idx = blockIdx.x * SCAN_B + tid;
    int v = (idx < NBKT) ? g_deg[idx] : 0;
    sh[tid] = v;
    __syncthreads();
#pragma unroll
    for (int off = 1; off < SCAN_B; off <<= 1) {
        int t = (tid >= off) ? sh[tid - off] : 0;
        __syncthreads();
        sh[tid] += t;
        __syncthreads();
    }
    if (tid == SCAN_B - 1) boff = atomicAdd(&g_total, sh[tid]);
    __syncthreads();
    if (idx < NBKT) g_rowptr[idx] = boff + sh[tid] - v;   // exclusive within partition
}
// scatter bumps rowptr in place; afterwards rowptr[b] == end of bucket b.
__global__ void scatter_kernel(const int* __restrict__ ei, const int* __restrict__ et) {
    int i = blockIdx.x * blockDim.x + threadIdx.x;
    if (i >= EE) return;
    int r = et[i];
    if (r >= NR) return;
    int b = r * NN + ei[i];
    int slot = atomicAdd(&g_rowptr[b], 1);
    g_adj[slot] = ei[EE + i];
}

// ================= conversions (pure; tiled+swizzled) =================
#define XCHUNKS (NN * 32)
#define BCHUNKS (5 * 16 * 1024)
__global__ void conv_all(const float* __restrict__ x,
                         const float* __restrict__ relW, const float* __restrict__ rootW,
                         const float* __restrict__ fc1w) {
    int gid = blockIdx.x * blockDim.x + threadIdx.x;
    if (gid < XCHUNKS) {
        int row = gid >> 5, cc = gid & 31;
        int kc = cc >> 3, c = cc & 7;
        int r = row & 127;
        const float* src = x + (size_t)row * 256 + cc * 8;
        float4 f0 = *(const float4*)src;
        float4 f1 = *(const float4*)(src + 4);
        uint4 hi, lo;
        hi.x = pack_hi(f0.x, f0.y, lo.x);
        hi.y = pack_hi(f0.z, f0.w, lo.y);
        hi.z = pack_hi(f1.x, f1.y, lo.z);
        hi.w = pack_hi(f1.z, f1.w, lo.w);
        size_t off = (size_t)((row >> 7) * 4 + kc) * TILE_BYTES + r * 128 + (((c ^ r) & 7) << 4);
        *(uint4*)((char*)g_xhi + off) = hi;
        *(uint4*)((char*)g_xlo + off) = lo;
        return;
    }
    int bid = gid - XCHUNKS;
    if (bid >= BCHUNKS) return;
    int g = bid >> 14;
    int r1 = bid & 16383;
    int cb = r1 >> 13;
    int r2 = r1 & 8191;
    int kc = r2 >> 10;
    int r3 = r2 & 1023;
    int row = r3 >> 3;
    int c = r3 & 7;
    int n = cb * 128 + row;
    int kbase = kc * 64 + c * 8;
    float v[8];
#pragma unroll
    for (int j = 0; j < 8; j++) {
        int k = kbase + j;
        if (g < 4)
            v[j] = (k < 256) ? relW[(((size_t)g * 5 + g) * 256 + k) * 256 + n]
                             : rootW[((size_t)g * 256 + (k - 256)) * 256 + n];
        else
            v[j] = fc1w[(size_t)k * 256 + n];
    }
    uint4 hi, lo;
    hi.x = pack_hi(v[0], v[1], lo.x);
    hi.y = pack_hi(v[2], v[3], lo.y);
    hi.z = pack_hi(v[4], v[5], lo.z);
    hi.w = pack_hi(v[6], v[7], lo.w);
    size_t off = (size_t)(g * 16 + cb * 8 + kc) * TILE_BYTES + row * 128 + (((c ^ row) & 7) << 4);
    *(uint4*)((char*)g_Bhi + off) = hi;
    *(uint4*)((char*)g_Blo + off) = lo;
}

// ================= fused CSR aggregation (tiled in/out) =================
__global__ void agg_csr(const __nv_bfloat16* __restrict__ inhiA, const __nv_bfloat16* __restrict__ inloA,
                        const __nv_bfloat16* __restrict__ inhiB, const __nv_bfloat16* __restrict__ inloB,
                        int relA, int relB,
                        __nv_bfloat16* __restrict__ outhi, __nv_bfloat16* __restrict__ outlo) {
    int w = (blockIdx.x * blockDim.x + threadIdx.x) >> 5;
    int lane = threadIdx.x & 31;
    if (w >= 2 * NN) return;
    int half = (w >= NN);
    int node = w - half * NN;
    int rel = half ? relB : relA;
    const char* hib = (const char*)(half ? inhiB : inhiA);
    const char* lob = (const char*)(half ? inloB : inloA);
    int b = rel * NN + node;
    int deg = g_deg[b];
    int end = g_rowptr[b];       // post-scatter: rowptr[b] == end
    int beg = end - deg;
    const int kc = lane >> 3, cc = lane & 7;
    float acc[8];
#pragma unroll
    for (int i = 0; i < 8; i++) acc[i] = 0.0f;
    for (int j = beg; j < end; j++) {
        int d = g_adj[j];
        int r = d & 127;
        size_t tb = (size_t)((d >> 7) * 4 + kc) * TILE_BYTES + r * 128 + (((cc ^ r) & 7) << 4);
        uint4 vh = *(const uint4*)(hib + tb);
        uint4 vl = *(const uint4*)(lob + tb);
        add_bf2(acc + 0, vh.x, vl.x);
        add_bf2(acc + 2, vh.y, vl.y);
        add_bf2(acc + 4, vh.z, vl.z);
        add_bf2(acc + 6, vh.w, vl.w);
    }
    float inv = 1.0f / fmaxf((float)deg, 1.0f);
    uint4 oh, ol;
    oh.x = pack_hi(acc[0] * inv, acc[1] * inv, ol.x);
    oh.y = pack_hi(acc[2] * inv, acc[3] * inv, ol.y);
    oh.z = pack_hi(acc[4] * inv, acc[5] * inv, ol.z);
    oh.w = pack_hi(acc[6] * inv, acc[7] * inv, ol.w);
    int r = node & 127;
    size_t ob = (size_t)((half * NBLK + (node >> 7)) * 4 + kc) * TILE_BYTES
              + r * 128 + (((cc ^ r) & 7) << 4);
    *(uint4*)((char*)outhi + ob) = oh;
    *(uint4*)((char*)outlo + ob) = ol;
}

// ================= bulk-copy MMA GEMM: 64x128 tiles, 48KB stages x4 =================
#define NSTAGE 4
#define STAGE_BYTES 49152
#define SMEM_BYTES (NSTAGE * STAGE_BYTES)   // 196608
#define NWARP 16

__global__ __launch_bounds__(512, 1)
void gemm_mma(const __nv_bfloat16* __restrict__ A1hi, const __nv_bfloat16* __restrict__ A1lo,
              const __nv_bfloat16* __restrict__ A2hi, const __nv_bfloat16* __restrict__ A2lo,
              int a2_global,
              const __nv_bfloat16* __restrict__ B0hi, const __nv_bfloat16* __restrict__ B0lo,
              const float* __restrict__ bias0,
              const __nv_bfloat16* __restrict__ B1hi, const __nv_bfloat16* __restrict__ B1lo,
              const float* __restrict__ bias1,
              float* __restrict__ Cf, __nv_bfloat16* __restrict__ Chi, __nv_bfloat16* __restrict__ Clo) {
    extern __shared__ __align__(16) char smem[];
    __shared__ __align__(8) uint64_t mbar[2 * NSTAGE];   // [full_s, empty_s] pairs
    const uint32_t sb = smem_u32(smem);
    const uint32_t sbar = smem_u32(mbar);
    const int tid = threadIdx.x;
    const int lane = tid & 31;
    const int wid = tid >> 5;                // 0..15
    const int wm = wid >> 2, wn = wid & 3;   // 4x4 warp grid, warp tile 16x32
    const int gblk = blockIdx.x;
    const int half = (gblk >= RB64) ? 1 : 0;
    const int lblk = gblk - half * RB64;     // 64-row block within half
    const int rb128 = lblk >> 1;             // layout tile row-block
    const int sub = lblk & 1;                // which 64-row half of the tile
    const int cb = blockIdx.y;
    const __nv_bfloat16* Bhi = half ? B1hi : B0hi;
    const __nv_bfloat16* Blo = half ? B1lo : B0lo;
    const float* bias = half ? bias1 : bias0;

    if (tid == 0) {
#pragma unroll
        for (int s = 0; s < NSTAGE; s++) {
            MBAR_INIT(sbar + s * 16, 1);          // full: tx-based
            MBAR_INIT(sbar + s * 16 + 8, NWARP);  // empty: one arrive per warp
        }
    }
    __syncthreads();

    auto issue = [&](int c) {
        const int s = c & (NSTAGE - 1);
        const uint32_t bar = sbar + s * 16;
        const uint32_t dst = sb + s * STAGE_BYTES;
        const int kc = (c < 4) ? c : (c - 4);
        size_t atile;
        const __nv_bfloat16 *ahb, *alb;
        if (c < 4) {
            atile = ((size_t)(half * NBLK + rb128) * 4 + kc);
            ahb = A1hi; alb = A1lo;
        } else {
            atile = a2_global ? ((size_t)(half * NBLK + rb128) * 4 + kc)
                              : ((size_t)rb128 * 4 + kc);
            ahb = A2hi; alb = A2lo;
        }
        const __nv_bfloat16* ah = ahb + atile * TILE_ELEMS + sub * 4096;   // 8KB slice
        const __nv_bfloat16* al = alb + atile * TILE_ELEMS + sub * 4096;
        const __nv_bfloat16* bh = Bhi + (size_t)(cb * 8 + c) * TILE_ELEMS;
        const __nv_bfloat16* bl = Blo + (size_t)(cb * 8 + c) * TILE_ELEMS;
        MBAR_EXPECT_TX(bar, STAGE_BYTES);
        bulk_g2s(dst,         ah, 8192,       bar);
        bulk_g2s(dst + 8192,  al, 8192,       bar);
        bulk_g2s(dst + 16384, bh, TILE_BYTES, bar);
        bulk_g2s(dst + 32768, bl, TILE_BYTES, bar);
    };

    if (tid == 0) { issue(0); issue(1); issue(2); issue(3); }

    float acc[4][4];
#pragma unroll
    for (int b = 0; b < 4; b++)
#pragma unroll
        for (int c = 0; c < 4; c++) acc[b][c] = 0.0f;

    const int rA0 = wm * 16 + (lane & 15);
    const int rB0 = wn * 32 + (lane & 15);
    const int ksub = (lane >> 4) << 3;

#pragma unroll 1
    for (int c = 0; c < 8; c++) {
        const int s = c & (NSTAGE - 1);
        MBAR_WAIT(sbar + s * 16, (c >> 2) & 1);          // full
        const uint32_t st = sb + s * STAGE_BYTES;
#pragma unroll
        for (int kk = 0; kk < 4; kk++) {
            const int kof = kk * 16 + ksub;
            uint32_t ahf[4], alf[4], bhf[2][4], blf[2][4];
            ldsm4(ahf, st + tileoff_b(rA0, kof));
            ldsm4(alf, st + 8192 + tileoff_b(rA0, kof));
#pragma unroll
            for (int np = 0; np < 2; np++) {
                ldsm4(bhf[np], st + 16384 + tileoff_b(rB0 + np * 16, kof));
                ldsm4(blf[np], st + 32768 + tileoff_b(rB0 + np * 16, kof));
            }
#pragma unroll
            for (int np = 0; np < 2; np++) {
                mma16816(acc[np * 2 + 0], ahf, bhf[np][0], bhf[np][2]);
                mma16816(acc[np * 2 + 1], ahf, bhf[np][1], bhf[np][3]);
                mma16816(acc[np * 2 + 0], ahf, blf[np][0], blf[np][2]);
                mma16816(acc[np * 2 + 1], ahf, blf[np][1], blf[np][3]);
                mma16816(acc[np * 2 + 0], alf, bhf[np][0], bhf[np][2]);
                mma16816(acc[np * 2 + 1], alf, bhf[np][1], bhf[np][3]);
            }
        }
        if (lane == 0) MBAR_ARRIVE(sbar + s * 16 + 8);       // warp done with stage s
        if (tid == 0 && c + NSTAGE < 8) {
            MBAR_WAIT(sbar + s * 16 + 8, (c >> 2) & 1);      // all warps done with stage s
            issue(c + NSTAGE);
        }
    }

    // ---------------- epilogue: direct global stores ----------------
    const int tq = lane & 3, trr = lane >> 2;
    float bv[4][2];
#pragma unroll
    for (int ni = 0; ni < 4; ni++) {
        int colg = cb * 128 + wn * 32 + ni * 8 + tq * 2;
        bv[ni][0] = __ldg(&bias[colg]);
        bv[ni][1] = __ldg(&bias[colg + 1]);
    }
#pragma unroll
    for (int hr = 0; hr < 2; hr++) {
        const int r = wm * 16 + trr + hr * 8;        // row within 64-row block
        const int rl = lblk * 64 + r;                // row within half
        if (rl >= NN) continue;
#pragma unroll
        for (int ni = 0; ni < 4; ni++) {
            float v0 = fmaxf(acc[ni][hr * 2 + 0] + bv[ni][0], 0.0f);
            float v1 = fmaxf(acc[ni][hr * 2 + 1] + bv[ni][1], 0.0f);
            const int colg = cb * 128 + wn * 32 + ni * 8 + tq * 2;
            if (Cf)
                *(float2*)(Cf + (size_t)(half * NN + rl) * 256 + colg) = make_float2(v0, v1);
            if (Chi) {
                uint32_t lo32;
                uint32_t hi32 = pack_hi(v0, v1, lo32);
                const int kcol = colg >> 6, kl = colg & 63;
                const size_t off = (size_t)((half * NBLK + (rl >> 7)) * 4 + kcol) * TILE_BYTES
                                 + tileoff_b(rl & 127, kl);
                *(uint32_t*)((char*)Chi + off) = hi32;
                *(uint32_t*)((char*)Clo + off) = lo32;
            }
        }
    }
}

// ---------------- fc2 (256->16) + log_softmax ----------------
__global__ void fc2_lsm_kernel(const float* __restrict__ H,
                               const float* __restrict__ W,
                               const float* __restrict__ b,
                               float* __restrict__ out, int M) {
    __shared__ float sw[16 * 256];
    const int tid = threadIdx.x;
    for (int i = tid; i < 16 * 256; i += blockDim.x) {
        int n = i >> 8, k = i & 255;
        sw[i] = W[k * 16 + n];
    }
    __syncthreads();

    const int warp = tid >> 5;
    const int lane = tid & 31;
    const int row = blockIdx.x * 8 + warp;
    if (row >= M) return;

    const float* hrow = H + (size_t)row * D;
    float acc[16];
#pragma unroll
    for (int n = 0; n < 16; n++) acc[n] = 0.0f;
#pragma unroll
    for (int kk = 0; kk < 8; kk++) {
        int k = lane + 32 * kk;
        float hv = hrow[k];
#pragma unroll
        for (int n = 0; n < 16; n++) acc[n] = fmaf(hv, sw[n * 256 + k], acc[n]);
    }
#pragma unroll
    for (int n = 0; n < 16; n++) {
#pragma unroll
        for (int o = 16; o > 0; o >>= 1)
            acc[n] += __shfl_xor_sync(0xFFFFFFFFu, acc[n], o);
    }
    if (lane == 0) {
        float v[16];
        float mx = -1e30f;
#pragma unroll
        for (int n = 0; n < 16; n++) { v[n] = acc[n] + b[n]; mx = fmaxf(mx, v[n]); }
        float s = 0.0f;
#pragma unroll
        for (int n = 0; n < 16; n++) s += expf(v[n] - mx);
        float l = logf(s);
        float* orow = out + (size_t)row * 16;
#pragma unroll
        for (int n = 0; n < 16; n++) orow[n] = v[n] - mx - l;
    }
}

// ================= host =================
template <typename T>
static T* sym(const void* symbol) {
    void* p = nullptr;
    cudaGetSymbolAddress(&p, symbol);
    return (T*)p;
}

extern "C" void kernel_launch(void* const* d_in, const int* in_sizes, int n_in,
                              void* d_out, int out_size) {
    const float* x     = (const float*)d_in[0];
    const int*   ei    = (const int*)  d_in[1];
    const int*   et    = (const int*)  d_in[2];
    const float* relW  = (const float*)d_in[3];
    const float* rootW = (const float*)d_in[4];
    const float* bias  = (const float*)d_in[5];
    const float* fc1w  = (const float*)d_in[6];
    const float* fc1b  = (const float*)d_in[7];
    const float* fc2w  = (const float*)d_in[8];
    const float* fc2b  = (const float*)d_in[9];
    float* out = (float*)d_out;

    __nv_bfloat16* xhi = sym<__nv_bfloat16>(g_xhi);
    __nv_bfloat16* xlo = sym<__nv_bfloat16>(g_xlo);
    __nv_bfloat16* ahi = sym<__nv_bfloat16>(g_agghi);
    __nv_bfloat16* alo = sym<__nv_bfloat16>(g_agglo);
    __nv_bfloat16* hhi = sym<__nv_bfloat16>(g_hhi);
    __nv_bfloat16* hlo = sym<__nv_bfloat16>(g_hlo);
    __nv_bfloat16* ehi = sym<__nv_bfloat16>(g_ehi);
    __nv_bfloat16* elo = sym<__nv_bfloat16>(g_elo);
    __nv_bfloat16* Bhi = sym<__nv_bfloat16>(g_Bhi);
    __nv_bfloat16* Blo = sym<__nv_bfloat16>(g_Blo);
    float* f1 = sym<float>(g_f1);

    cudaFuncSetAttribute(gemm_mma, cudaFuncAttributeMaxDynamicSharedMemorySize, SMEM_BYTES);

    const size_t GB = 16 * TILE_ELEMS;   // B elems per gemm

    // Fork: CSR chain on s0, conversions on s2 (independent).
    cudaStream_t s0 = 0, s2;
    cudaStreamCreate(&s2);
    cudaEvent_t evFork, evJoin;
    cudaEventCreateWithFlags(&evFork, cudaEventDisableTiming);
    cudaEventCreateWithFlags(&evJoin, cudaEventDisableTiming);

    cudaEventRecord(evFork, s0);
    cudaStreamWaitEvent(s2, evFork, 0);
    conv_all<<<(XCHUNKS + BCHUNKS + 255) / 256, 256, 0, s2>>>(x, relW, rootW, fc1w);
    cudaEventRecord(evJoin, s2);

    // main stream: CSR build
    zero_deg_kernel<<<(NBKT + 255) / 256, 256, 0, s0>>>();
    hist_kernel<<<(EE + 255) / 256, 256, 0, s0>>>(ei, et);
    scan_fused<<<SCAN_NB, SCAN_B, 0, s0>>>();
    scatter_kernel<<<(EE + 255) / 256, 256, 0, s0>>>(ei, et);

    // join: agg needs CSR + xhi/xlo; gemm needs B tiles
    cudaStreamWaitEvent(s0, evJoin, 0);

    const dim3 ggrid2(2 * RB64, 2);
    const dim3 ggrid1(RB64, 2);
    const int aggBlocks = (2 * NN * 32 + 255) / 256;

    // stage A (convs {0,2} on x)
    agg_csr<<<aggBlocks, 256, 0, s0>>>(xhi, xlo, xhi, xlo, 0, 2, ahi, alo);
    gemm_mma<<<ggrid2, 512, SMEM_BYTES, s0>>>(
        ahi, alo, xhi, xlo, /*a2_global=*/0,
        Bhi + 0 * GB, Blo + 0 * GB, bias + 0 * 256,
        Bhi + 2 * GB, Blo + 2 * GB, bias + 2 * 256,
        nullptr, hhi, hlo);

    // stage B (convs {1,3} on stage-A halves)
    agg_csr<<<aggBlocks, 256, 0, s0>>>(hhi, hlo, hhi + HALF_OFF, hlo + HALF_OFF, 1, 3, ahi, alo);
    gemm_mma<<<ggrid2, 512, SMEM_BYTES, s0>>>(
        ahi, alo, hhi, hlo, /*a2_global=*/1,
        Bhi + 1 * GB, Blo + 1 * GB, bias + 1 * 256,
        Bhi + 3 * GB, Blo + 3 * GB, bias + 3 * 256,
        nullptr, ehi, elo);

    // fc1: [e0 | e1] -> f1 (f32, relu)
    gemm_mma<<<ggrid1, 512, SMEM_BYTES, s0>>>(
        ehi, elo, ehi + HALF_OFF, elo + HALF_OFF, /*a2_global=*/0,
        Bhi + 4 * GB, Blo + 4 * GB, fc1b,
        Bhi + 4 * GB, Blo + 4 * GB, fc1b,
        f1, nullptr, nullptr);

    // fc2 + log_softmax
    fc2_lsm_kernel<<<(NN + 7) / 8, 256, 0, s0>>>(f1, fc2w, fc2b, out, NN);
}

// round 17
// speedup vs baseline: 1.5094x; 1.0091x over previous
#include <cuda_runtime.h>
#include <cuda_bf16.h>
#include <cstdint>
#include <math.h>

#define NN 20000
#define D  256
#define EE 500000
#define NR 4
#define NBKT (NR * NN)
#define NBLK 157                 // 128-row layout tiles per 20000-row half
#define RB64 313                 // 64-row GEMM blocks per half
#define TILE_ELEMS 8192          // 128 rows x 64 k bf16
#define TILE_BYTES 16384
#define ATILES (NBLK * 4)        // tiles per 256-wide half-array (628)
#define HALF_OFF ((size_t)ATILES * TILE_ELEMS)
#define SCAN_B 1024
#define SCAN_NB ((NBKT + SCAN_B - 1) / SCAN_B)   // 79

// ---------------- scratch (no allocations allowed) ----------------
__device__ int g_deg[NBKT];
__device__ int g_rowptr[NBKT];
__device__ int g_total;
__device__ int g_adj[EE];

__device__ __nv_bfloat16 g_xhi[ATILES * TILE_ELEMS], g_xlo[ATILES * TILE_ELEMS];
__device__ __nv_bfloat16 g_agghi[2 * ATILES * TILE_ELEMS], g_agglo[2 * ATILES * TILE_ELEMS];
__device__ __nv_bfloat16 g_hhi[2 * ATILES * TILE_ELEMS], g_hlo[2 * ATILES * TILE_ELEMS];
__device__ __nv_bfloat16 g_ehi[2 * ATILES * TILE_ELEMS], g_elo[2 * ATILES * TILE_ELEMS];
__device__ float g_f1[NN * D];
// B: [gemm 5][colblock 2][kc 8][tile]
__device__ __nv_bfloat16 g_Bhi[5 * 16 * TILE_ELEMS], g_Blo[5 * 16 * TILE_ELEMS];

// ================= helpers =================
__device__ __forceinline__ uint32_t smem_u32(const void* p) {
    uint32_t a;
    asm("{ .reg .u64 t; cvta.to.shared.u64 t, %1; cvt.u32.u64 %0, t; }" : "=r"(a) : "l"(p));
    return a;
}
// byte offset of (row r, col k) inside a 128x64 bf16 tile with XOR-swizzled 128B rows
__device__ __forceinline__ uint32_t tileoff_b(int r, int k) {
    return (uint32_t)(r * 128 + ((((k >> 3) ^ r) & 7) << 4) + ((k & 7) << 1));
}
#define MBAR_INIT(addr, cnt) \
    asm volatile("mbarrier.init.shared.b64 [%0], %1;" :: "r"(addr), "r"(cnt) : "memory")
#define MBAR_ARRIVE(addr) \
    asm volatile("mbarrier.arrive.shared.b64 _, [%0];" :: "r"(addr) : "memory")
#define MBAR_EXPECT_TX(addr, bytes) \
    asm volatile("mbarrier.arrive.expect_tx.shared.b64 _, [%0], %1;" :: "r"(addr), "r"(bytes) : "memory")
#define MBAR_WAIT(addr, parity) do {                                              \
    uint32_t _m = (addr); uint32_t _p = (parity); uint32_t _done;                 \
    asm volatile("{\n\t.reg .pred p;\n\t"                                         \
        "mbarrier.try_wait.parity.acquire.cta.shared::cta.b64 p, [%1], %2;\n\t"   \
        "selp.b32 %0, 1, 0, p;\n\t}"                                              \
        : "=r"(_done) : "r"(_m), "r"(_p) : "memory");                             \
    if (!_done) {                                                                 \
        asm volatile("{\n\t.reg .pred P1;\n\t"                                    \
            "WL_%=:\n\t"                                                          \
            "mbarrier.try_wait.parity.acquire.cta.shared::cta.b64 P1, [%0], %1, 0x989680;\n\t" \
            "@P1 bra.uni WD_%=;\n\t"                                              \
            "bra.uni WL_%=;\n\t"                                                  \
            "WD_%=:\n\t}" :: "r"(_m), "r"(_p) : "memory");                        \
    }                                                                             \
} while (0)
__device__ __forceinline__ void bulk_g2s(uint32_t dst, const void* src, uint32_t bytes, uint32_t mbar) {
    asm volatile("cp.async.bulk.shared::cluster.global.mbarrier::complete_tx::bytes [%0], [%1], %2, [%3];"
                 :: "r"(dst), "l"(__cvta_generic_to_global(src)), "r"(bytes), "r"(mbar) : "memory");
}
__device__ __forceinline__ void ldsm4(uint32_t* r, uint32_t addr) {
    asm volatile("ldmatrix.sync.aligned.m8n8.x4.shared.b16 {%0,%1,%2,%3}, [%4];"
                 : "=r"(r[0]), "=r"(r[1]), "=r"(r[2]), "=r"(r[3]) : "r"(addr));
}
__device__ __forceinline__ void mma16816(float* c, const uint32_t* a, uint32_t b0, uint32_t b1) {
    asm volatile("mma.sync.aligned.m16n8k16.row.col.f32.bf16.bf16.f32 "
                 "{%0,%1,%2,%3}, {%4,%5,%6,%7}, {%8,%9}, {%0,%1,%2,%3};"
                 : "+f"(c[0]), "+f"(c[1]), "+f"(c[2]), "+f"(c[3])
                 : "r"(a[0]), "r"(a[1]), "r"(a[2]), "r"(a[3]), "r"(b0), "r"(b1));
}
__device__ __forceinline__ void add_bf2(float* a, uint32_t h, uint32_t l) {
    __nv_bfloat162 hh = *(__nv_bfloat162*)&h, ll = *(__nv_bfloat162*)&l;
    float2 fh = __bfloat1622float2(hh), fl = __bfloat1622float2(ll);
    a[0] += fh.x + fl.x;
    a[1] += fh.y + fl.y;
}
__device__ __forceinline__ uint32_t pack_hi(float v0, float v1, uint32_t& lo_out) {
    __nv_bfloat16 h0 = __float2bfloat16(v0);
    __nv_bfloat16 h1 = __float2bfloat16(v1);
    __nv_bfloat16 l0 = __float2bfloat16(v0 - __bfloat162float(h0));
    __nv_bfloat16 l1 = __float2bfloat16(v1 - __bfloat162float(h1));
    lo_out = (uint32_t)__bfloat16_as_ushort(l0) | ((uint32_t)__bfloat16_as_ushort(l1) << 16);
    return (uint32_t)__bfloat16_as_ushort(h0) | ((uint32_t)__bfloat16_as_ushort(h1) << 16);
}

// ================= CSR build =================
__global__ void zero_deg_kernel() {
    int i = blockIdx.x * blockDim.x + threadIdx.x;
    if (i < NBKT) g_deg[i] = 0;
    if (i == 0) g_total = 0;
}
// 2 edges per thread, int2 loads (EE even; harness buffers 256B-aligned)
__global__ void hist_kernel(const int* __restrict__ ei, const int* __restrict__ et) {
    int i = (blockIdx.x * blockDim.x + threadIdx.x) * 2;
    if (i >= EE) return;
    int2 rr = *(const int2*)(et + i);
    int2 ss = *(const int2*)(ei + i);
    if (rr.x < NR) atomicAdd(&g_deg[rr.x * NN + ss.x], 1);
    if (rr.y < NR) atomicAdd(&g_deg[rr.y * NN + ss.y], 1);
}
__global__ void scan_fused() {
    __shared__ int sh[SCAN_B];
    __shared__ int boff;
    const int tid = threadIdx.x;
    const int idx = blockIdx.x * SCAN_B + tid;
    int v = (idx < NBKT) ? g_deg[idx] : 0;
    sh[tid] = v;
    __syncthreads();
#pragma unroll
    for (int off = 1; off < SCAN_B; off <<= 1) {
        int t = (tid >= off) ? sh[tid - off] : 0;
        __syncthreads();
        sh[tid] += t;
        __syncthreads();
    }
    if (tid == SCAN_B - 1) boff = atomicAdd(&g_total, sh[tid]);
    __syncthreads();
    if (idx < NBKT) g_rowptr[idx] = boff + sh[tid] - v;   // exclusive within partition
}
// scatter bumps rowptr in place; afterwards rowptr[b] == end of bucket b.
__global__ void scatter_kernel(const int* __restrict__ ei, const int* __restrict__ et) {
    int i = (blockIdx.x * blockDim.x + threadIdx.x) * 2;
    if (i >= EE) return;
    int2 rr = *(const int2*)(et + i);
    int2 ss = *(const int2*)(ei + i);
    int2 dd = *(const int2*)(ei + EE + i);
    if (rr.x < NR) {
        int slot = atomicAdd(&g_rowptr[rr.x * NN + ss.x], 1);
        g_adj[slot] = dd.x;
    }
    if (rr.y < NR) {
        int slot = atomicAdd(&g_rowptr[rr.y * NN + ss.y], 1);
        g_adj[slot] = dd.y;
    }
}

// ================= conversions (pure; tiled+swizzled) =================
#define XCHUNKS (NN * 32)
#define BCHUNKS (5 * 16 * 1024)
__global__ void conv_all(const float* __restrict__ x,
                         const float* __restrict__ relW, const float* __restrict__ rootW,
                         const float* __restrict__ fc1w) {
    int gid = blockIdx.x * blockDim.x + threadIdx.x;
    if (gid < XCHUNKS) {
        int row = gid >> 5, cc = gid & 31;
        int kc = cc >> 3, c = cc & 7;
        int r = row & 127;
        const float* src = x + (size_t)row * 256 + cc * 8;
        float4 f0 = *(const float4*)src;
        float4 f1 = *(const float4*)(src + 4);
        uint4 hi, lo;
        hi.x = pack_hi(f0.x, f0.y, lo.x);
        hi.y = pack_hi(f0.z, f0.w, lo.y);
        hi.z = pack_hi(f1.x, f1.y, lo.z);
        hi.w = pack_hi(f1.z, f1.w, lo.w);
        size_t off = (size_t)((row >> 7) * 4 + kc) * TILE_BYTES + r * 128 + (((c ^ r) & 7) << 4);
        *(uint4*)((char*)g_xhi + off) = hi;
        *(uint4*)((char*)g_xlo + off) = lo;
        return;
    }
    int bid = gid - XCHUNKS;
    if (bid >= BCHUNKS) return;
    int g = bid >> 14;
    int r1 = bid & 16383;
    int cb = r1 >> 13;
    int r2 = r1 & 8191;
    int kc = r2 >> 10;
    int r3 = r2 & 1023;
    int row = r3 >> 3;
    int c = r3 & 7;
    int n = cb * 128 + row;
    int kbase = kc * 64 + c * 8;
    float v[8];
#pragma unroll
    for (int j = 0; j < 8; j++) {
        int k = kbase + j;
        if (g < 4)
            v[j] = (k < 256) ? relW[(((size_t)g * 5 + g) * 256 + k) * 256 + n]
                             : rootW[((size_t)g * 256 + (k - 256)) * 256 + n];
        else
            v[j] = fc1w[(size_t)k * 256 + n];
    }
    uint4 hi, lo;
    hi.x = pack_hi(v[0], v[1], lo.x);
    hi.y = pack_hi(v[2], v[3], lo.y);
    hi.z = pack_hi(v[4], v[5], lo.z);
    hi.w = pack_hi(v[6], v[7], lo.w);
    size_t off = (size_t)(g * 16 + cb * 8 + kc) * TILE_BYTES + row * 128 + (((c ^ row) & 7) << 4);
    *(uint4*)((char*)g_Bhi + off) = hi;
    *(uint4*)((char*)g_Blo + off) = lo;
}

// ================= fused CSR aggregation (tiled in/out, 2-edge ILP) =================
__global__ void agg_csr(const __nv_bfloat16* __restrict__ inhiA, const __nv_bfloat16* __restrict__ inloA,
                        const __nv_bfloat16* __restrict__ inhiB, const __nv_bfloat16* __restrict__ inloB,
                        int relA, int relB,
                        __nv_bfloat16* __restrict__ outhi, __nv_bfloat16* __restrict__ outlo) {
    int w = (blockIdx.x * blockDim.x + threadIdx.x) >> 5;
    int lane = threadIdx.x & 31;
    if (w >= 2 * NN) return;
    int half = (w >= NN);
    int node = w - half * NN;
    int rel = half ? relB : relA;
    const char* hib = (const char*)(half ? inhiB : inhiA);
    const char* lob = (const char*)(half ? inloB : inloA);
    int b = rel * NN + node;
    int deg = g_deg[b];
    int end = g_rowptr[b];       // post-scatter: rowptr[b] == end
    int beg = end - deg;
    const int kc = lane >> 3, cc = lane & 7;
    float acc[8];
#pragma unroll
    for (int i = 0; i < 8; i++) acc[i] = 0.0f;
    int j = beg;
    for (; j + 2 <= end; j += 2) {                 // 2-edge ILP
        int d0 = g_adj[j], d1 = g_adj[j + 1];
        int r0 = d0 & 127, r1 = d1 & 127;
        size_t t0 = (size_t)((d0 >> 7) * 4 + kc) * TILE_BYTES + r0 * 128 + (((cc ^ r0) & 7) << 4);
        size_t t1 = (size_t)((d1 >> 7) * 4 + kc) * TILE_BYTES + r1 * 128 + (((cc ^ r1) & 7) << 4);
        uint4 vh0 = *(const uint4*)(hib + t0);
        uint4 vl0 = *(const uint4*)(lob + t0);
        uint4 vh1 = *(const uint4*)(hib + t1);
        uint4 vl1 = *(const uint4*)(lob + t1);
        add_bf2(acc + 0, vh0.x, vl0.x);
        add_bf2(acc + 2, vh0.y, vl0.y);
        add_bf2(acc + 4, vh0.z, vl0.z);
        add_bf2(acc + 6, vh0.w, vl0.w);
        add_bf2(acc + 0, vh1.x, vl1.x);
        add_bf2(acc + 2, vh1.y, vl1.y);
        add_bf2(acc + 4, vh1.z, vl1.z);
        add_bf2(acc + 6, vh1.w, vl1.w);
    }
    if (j < end) {
        int d = g_adj[j];
        int r = d & 127;
        size_t tb = (size_t)((d >> 7) * 4 + kc) * TILE_BYTES + r * 128 + (((cc ^ r) & 7) << 4);
        uint4 vh = *(const uint4*)(hib + tb);
        uint4 vl = *(const uint4*)(lob + tb);
        add_bf2(acc + 0, vh.x, vl.x);
        add_bf2(acc + 2, vh.y, vl.y);
        add_bf2(acc + 4, vh.z, vl.z);
        add_bf2(acc + 6, vh.w, vl.w);
    }
    float inv = 1.0f / fmaxf((float)deg, 1.0f);
    uint4 oh, ol;
    oh.x = pack_hi(acc[0] * inv, acc[1] * inv, ol.x);
    oh.y = pack_hi(acc[2] * inv, acc[3] * inv, ol.y);
    oh.z = pack_hi(acc[4] * inv, acc[5] * inv, ol.z);
    oh.w = pack_hi(acc[6] * inv, acc[7] * inv, ol.w);
    int r = node & 127;
    size_t ob = (size_t)((half * NBLK + (node >> 7)) * 4 + kc) * TILE_BYTES
              + r * 128 + (((cc ^ r) & 7) << 4);
    *(uint4*)((char*)outhi + ob) = oh;
    *(uint4*)((char*)outlo + ob) = ol;
}

// ================= bulk-copy MMA GEMM: 64x128 tiles, 48KB stages x4 =================
#define NSTAGE 4
#define STAGE_BYTES 49152
#define SMEM_BYTES (NSTAGE * STAGE_BYTES)   // 196608
#define NWARP 16

__global__ __launch_bounds__(512, 1)
void gemm_mma(const __nv_bfloat16* __restrict__ A1hi, const __nv_bfloat16* __restrict__ A1lo,
              const __nv_bfloat16* __restrict__ A2hi, const __nv_bfloat16* __restrict__ A2lo,
              int a2_global,
              const __nv_bfloat16* __restrict__ B0hi, const __nv_bfloat16* __restrict__ B0lo,
              const float* __restrict__ bias0,
              const __nv_bfloat16* __restrict__ B1hi, const __nv_bfloat16* __restrict__ B1lo,
              const float* __restrict__ bias1,
              float* __restrict__ Cf, __nv_bfloat16* __restrict__ Chi, __nv_bfloat16* __restrict__ Clo) {
    extern __shared__ __align__(16) char smem[];
    __shared__ __align__(8) uint64_t mbar[2 * NSTAGE];   // [full_s, empty_s] pairs
    const uint32_t sb = smem_u32(smem);
    const uint32_t sbar = smem_u32(mbar);
    const int tid = threadIdx.x;
    const int lane = tid & 31;
    const int wid = tid >> 5;                // 0..15
    const int wm = wid >> 2, wn = wid & 3;   // 4x4 warp grid, warp tile 16x32
    const int gblk = blockIdx.x;
    const int half = (gblk >= RB64) ? 1 : 0;
    const int lblk = gblk - half * RB64;     // 64-row block within half
    const int rb128 = lblk >> 1;             // layout tile row-block
    const int sub = lblk & 1;                // which 64-row half of the tile
    const int cb = blockIdx.y;
    const __nv_bfloat16* Bhi = half ? B1hi : B0hi;
    const __nv_bfloat16* Blo = half ? B1lo : B0lo;
    const float* bias = half ? bias1 : bias0;

    if (tid == 0) {
#pragma unroll
        for (int s = 0; s < NSTAGE; s++) {
            MBAR_INIT(sbar + s * 16, 1);          // full: tx-based
            MBAR_INIT(sbar + s * 16 + 8, NWARP);  // empty: one arrive per warp
        }
    }
    __syncthreads();

    auto issue = [&](int c) {
        const int s = c & (NSTAGE - 1);
        const uint32_t bar = sbar + s * 16;
        const uint32_t dst = sb + s * STAGE_BYTES;
        const int kc = (c < 4) ? c : (c - 4);
        size_t atile;
        const __nv_bfloat16 *ahb, *alb;
        if (c < 4) {
            atile = ((size_t)(half * NBLK + rb128) * 4 + kc);
            ahb = A1hi; alb = A1lo;
        } else {
            atile = a2_global ? ((size_t)(half * NBLK + rb128) * 4 + kc)
                              : ((size_t)rb128 * 4 + kc);
            ahb = A2hi; alb = A2lo;
        }
        const __nv_bfloat16* ah = ahb + atile * TILE_ELEMS + sub * 4096;   // 8KB slice
        const __nv_bfloat16* al = alb + atile * TILE_ELEMS + sub * 4096;
        const __nv_bfloat16* bh = Bhi + (size_t)(cb * 8 + c) * TILE_ELEMS;
        const __nv_bfloat16* bl = Blo + (size_t)(cb * 8 + c) * TILE_ELEMS;
        MBAR_EXPECT_TX(bar, STAGE_BYTES);
        bulk_g2s(dst,         ah, 8192,       bar);
        bulk_g2s(dst + 8192,  al, 8192,       bar);
        bulk_g2s(dst + 16384, bh, TILE_BYTES, bar);
        bulk_g2s(dst + 32768, bl, TILE_BYTES, bar);
    };

    if (tid == 0) { issue(0); issue(1); issue(2); issue(3); }

    float acc[4][4];
#pragma unroll
    for (int b = 0; b < 4; b++)
#pragma unroll
        for (int c = 0; c < 4; c++) acc[b][c] = 0.0f;

    const int rA0 = wm * 16 + (lane & 15);
    const int rB0 = wn * 32 + (lane & 15);
    const int ksub = (lane >> 4) << 3;

#pragma unroll 1
    for (int c = 0; c < 8; c++) {
        const int s = c & (NSTAGE - 1);
        MBAR_WAIT(sbar + s * 16, (c >> 2) & 1);          // full
        const uint32_t st = sb + s * STAGE_BYTES;
#pragma unroll
        for (int kk = 0; kk < 4; kk++) {
            const int kof = kk * 16 + ksub;
            uint32_t ahf[4], alf[4], bhf[2][4], blf[2][4];
            ldsm4(ahf, st + tileoff_b(rA0, kof));
            ldsm4(alf, st + 8192 + tileoff_b(rA0, kof));
#pragma unroll
            for (int np = 0; np < 2; np++) {
                ldsm4(bhf[np], st + 16384 + tileoff_b(rB0 + np * 16, kof));
                ldsm4(blf[np], st + 32768 + tileoff_b(rB0 + np * 16, kof));
            }
#pragma unroll
            for (int np = 0; np < 2; np++) {
                mma16816(acc[np * 2 + 0], ahf, bhf[np][0], bhf[np][2]);
                mma16816(acc[np * 2 + 1], ahf, bhf[np][1], bhf[np][3]);
                mma16816(acc[np * 2 + 0], ahf, blf[np][0], blf[np][2]);
                mma16816(acc[np * 2 + 1], ahf, blf[np][1], blf[np][3]);
                mma16816(acc[np * 2 + 0], alf, bhf[np][0], bhf[np][2]);
                mma16816(acc[np * 2 + 1], alf, bhf[np][1], bhf[np][3]);
            }
        }
        if (lane == 0) MBAR_ARRIVE(sbar + s * 16 + 8);       // warp done with stage s
        if (tid == 0 && c + NSTAGE < 8) {
            MBAR_WAIT(sbar + s * 16 + 8, (c >> 2) & 1);      // all warps done with stage s
            issue(c + NSTAGE);
        }
    }

    // ---------------- epilogue: direct global stores ----------------
    const int tq = lane & 3, trr = lane >> 2;
    float bv[4][2];
#pragma unroll
    for (int ni = 0; ni < 4; ni++) {
        int colg = cb * 128 + wn * 32 + ni * 8 + tq * 2;
        bv[ni][0] = __ldg(&bias[colg]);
        bv[ni][1] = __ldg(&bias[colg + 1]);
    }
#pragma unroll
    for (int hr = 0; hr < 2; hr++) {
        const int r = wm * 16 + trr + hr * 8;        // row within 64-row block
        const int rl = lblk * 64 + r;                // row within half
        if (rl >= NN) continue;
#pragma unroll
        for (int ni = 0; ni < 4; ni++) {
            float v0 = fmaxf(acc[ni][hr * 2 + 0] + bv[ni][0], 0.0f);
            float v1 = fmaxf(acc[ni][hr * 2 + 1] + bv[ni][1], 0.0f);
            const int colg = cb * 128 + wn * 32 + ni * 8 + tq * 2;
            if (Cf)
                *(float2*)(Cf + (size_t)(half * NN + rl) * 256 + colg) = make_float2(v0, v1);
            if (Chi) {
                uint32_t lo32;
                uint32_t hi32 = pack_hi(v0, v1, lo32);
                const int kcol = colg >> 6, kl = colg & 63;
                const size_t off = (size_t)((half * NBLK + (rl >> 7)) * 4 + kcol) * TILE_BYTES
                                 + tileoff_b(rl & 127, kl);
                *(uint32_t*)((char*)Chi + off) = hi32;
                *(uint32_t*)((char*)Clo + off) = lo32;
            }
        }
    }
}

// ---------------- fc2 (256->16) + log_softmax ----------------
__global__ void fc2_lsm_kernel(const float* __restrict__ H,
                               const float* __restrict__ W,
                               const float* __restrict__ b,
                               float* __restrict__ out, int M) {
    __shared__ float sw[16 * 256];
    const int tid = threadIdx.x;
    for (int i = tid; i < 16 * 256; i += blockDim.x) {
        int n = i >> 8, k = i & 255;
        sw[i] = W[k * 16 + n];
    }
    __syncthreads();

    const int warp = tid >> 5;
    const int lane = tid & 31;
    const int row = blockIdx.x * 8 + warp;
    if (row >= M) return;

    const float* hrow = H + (size_t)row * D;
    float acc[16];
#pragma unroll
    for (int n = 0; n < 16; n++) acc[n] = 0.0f;
#pragma unroll
    for (int kk = 0; kk < 8; kk++) {
        int k = lane + 32 * kk;
        float hv = hrow[k];
#pragma unroll
        for (int n = 0; n < 16; n++) acc[n] = fmaf(hv, sw[n * 256 + k], acc[n]);
    }
#pragma unroll
    for (int n = 0; n < 16; n++) {
#pragma unroll
        for (int o = 16; o > 0; o >>= 1)
            acc[n] += __shfl_xor_sync(0xFFFFFFFFu, acc[n], o);
    }
    if (lane == 0) {
        float v[16];
        float mx = -1e30f;
#pragma unroll
        for (int n = 0; n < 16; n++) { v[n] = acc[n] + b[n]; mx = fmaxf(mx, v[n]); }
        float s = 0.0f;
#pragma unroll
        for (int n = 0; n < 16; n++) s += expf(v[n] - mx);
        float l = logf(s);
        float* orow = out + (size_t)row * 16;
#pragma unroll
        for (int n = 0; n < 16; n++) orow[n] = v[n] - mx - l;
    }
}

// ================= host =================
template <typename T>
static T* sym(const void* symbol) {
    void* p = nullptr;
    cudaGetSymbolAddress(&p, symbol);
    return (T*)p;
}

extern "C" void kernel_launch(void* const* d_in, const int* in_sizes, int n_in,
                              void* d_out, int out_size) {
    const float* x     = (const float*)d_in[0];
    const int*   ei    = (const int*)  d_in[1];
    const int*   et    = (const int*)  d_in[2];
    const float* relW  = (const float*)d_in[3];
    const float* rootW = (const float*)d_in[4];
    const float* bias  = (const float*)d_in[5];
    const float* fc1w  = (const float*)d_in[6];
    const float* fc1b  = (const float*)d_in[7];
    const float* fc2w  = (const float*)d_in[8];
    const float* fc2b  = (const float*)d_in[9];
    float* out = (float*)d_out;

    __nv_bfloat16* xhi = sym<__nv_bfloat16>(g_xhi);
    __nv_bfloat16* xlo = sym<__nv_bfloat16>(g_xlo);
    __nv_bfloat16* ahi = sym<__nv_bfloat16>(g_agghi);
    __nv_bfloat16* alo = sym<__nv_bfloat16>(g_agglo);
    __nv_bfloat16* hhi = sym<__nv_bfloat16>(g_hhi);
    __nv_bfloat16* hlo = sym<__nv_bfloat16>(g_hlo);
    __nv_bfloat16* ehi = sym<__nv_bfloat16>(g_ehi);
    __nv_bfloat16* elo = sym<__nv_bfloat16>(g_elo);
    __nv_bfloat16* Bhi = sym<__nv_bfloat16>(g_Bhi);
    __nv_bfloat16* Blo = sym<__nv_bfloat16>(g_Blo);
    float* f1 = sym<float>(g_f1);

    cudaFuncSetAttribute(gemm_mma, cudaFuncAttributeMaxDynamicSharedMemorySize, SMEM_BYTES);

    const size_t GB = 16 * TILE_ELEMS;   // B elems per gemm

    // Fork: CSR chain on s0, conversions on s2 (independent).
    cudaStream_t s0 = 0, s2;
    cudaStreamCreate(&s2);
    cudaEvent_t evFork, evJoin;
    cudaEventCreateWithFlags(&evFork, cudaEventDisableTiming);
    cudaEventCreateWithFlags(&evJoin, cudaEventDisableTiming);

    cudaEventRecord(evFork, s0);
    cudaStreamWaitEvent(s2, evFork, 0);
    conv_all<<<(XCHUNKS + BCHUNKS + 255) / 256, 256, 0, s2>>>(x, relW, rootW, fc1w);
    cudaEventRecord(evJoin, s2);

    // main stream: CSR build
    zero_deg_kernel<<<(NBKT + 255) / 256, 256, 0, s0>>>();
    hist_kernel<<<(EE / 2 + 255) / 256, 256, 0, s0>>>(ei, et);
    scan_fused<<<SCAN_NB, SCAN_B, 0, s0>>>();
    scatter_kernel<<<(EE / 2 + 255) / 256, 256, 0, s0>>>(ei, et);

    // join: agg needs CSR + xhi/xlo; gemm needs B tiles
    cudaStreamWaitEvent(s0, evJoin, 0);

    const dim3 ggrid2(2 * RB64, 2);
    const dim3 ggrid1(RB64, 2);
    const int aggBlocks = (2 * NN * 32 + 255) / 256;

    // stage A (convs {0,2} on x)
    agg_csr<<<aggBlocks, 256, 0, s0>>>(xhi, xlo, xhi, xlo, 0, 2, ahi, alo);
    gemm_mma<<<ggrid2, 512, SMEM_BYTES, s0>>>(
        ahi, alo, xhi, xlo, /*a2_global=*/0,
        Bhi + 0 * GB, Blo + 0 * GB, bias + 0 * 256,
        Bhi + 2 * GB, Blo + 2 * GB, bias + 2 * 256,
        nullptr, hhi, hlo);

    // stage B (convs {1,3} on stage-A halves)
    agg_csr<<<aggBlocks, 256, 0, s0>>>(hhi, hlo, hhi + HALF_OFF, hlo + HALF_OFF, 1, 3, ahi, alo);
    gemm_mma<<<ggrid2, 512, SMEM_BYTES, s0>>>(
        ahi, alo, hhi, hlo, /*a2_global=*/1,
        Bhi + 1 * GB, Blo + 1 * GB, bias + 1 * 256,
        Bhi + 3 * GB, Blo + 3 * GB, bias + 3 * 256,
        nullptr, ehi, elo);

    // fc1: [e0 | e1] -> f1 (f32, relu)
    gemm_mma<<<ggrid1, 512, SMEM_BYTES, s0>>>(
        ehi, elo, ehi + HALF_OFF, elo + HALF_OFF, /*a2_global=*/0,
        Bhi + 4 * GB, Blo + 4 * GB, fc1b,
        Bhi + 4 * GB, Blo + 4 * GB, fc1b,
        f1, nullptr, nullptr);

    // fc2 + log_softmax
    fc2_lsm_kernel<<<(NN + 7) / 8, 256, 0, s0>>>(f1, fc2w, fc2b, out, NN);
}